// round 2
// baseline (speedup 1.0000x reference)
#include <cuda_runtime.h>

#define NA      8000
#define MP      1200000
#define NCDIM   8
#define NCELL   512
#define ROWCAP  192
#define NWORDS  250   /* 8000 / 32 */

// ---------------- device scratch (no allocations allowed) ----------------
__device__ float4 g_pos4[NA];        // original order: x,y,z,|p|^2
__device__ float4 g_pos4s[NA];       // cell-sorted copy
__device__ int    g_orig[NA];        // sorted slot -> original atom index
__device__ int    g_cellid[NA];
__device__ int    g_ccount[NCELL];
__device__ int    g_cstart[NCELL + 1];
__device__ int    g_ccursor[NCELL];
__device__ int    g_rcount[NA];
__device__ int    g_roff[NA];
__device__ int    g_scratch[NA * ROWCAP];

__device__ __forceinline__ int cellco(float x) {
    int c = (int)(x * 0.2f);
    return min(7, max(0, c));
}

// ---------------- kernels ----------------
__global__ void k_zero(float* __restrict__ out, int n) {
    int i = blockIdx.x * blockDim.x + threadIdx.x;
    int stride = gridDim.x * blockDim.x;
    for (int k = i; k < n; k += stride) out[k] = 0.0f;
    if (i < NCELL) g_ccount[i] = 0;
}

__global__ void k_prep(const float* __restrict__ pos) {
    int i = blockIdx.x * blockDim.x + threadIdx.x;
    if (i >= NA) return;
    float x = pos[3 * i + 0];
    float y = pos[3 * i + 1];
    float z = pos[3 * i + 2];
    // sq = (x*x + y*y) + z*z, strict fp32, NO FMA (XLA mul+reduce fusion
    // emits separate fmul/fadd; LLVM won't contract them)
    float sq = __fadd_rn(__fadd_rn(__fmul_rn(x, x), __fmul_rn(y, y)), __fmul_rn(z, z));
    g_pos4[i] = make_float4(x, y, z, sq);
    int c = (cellco(z) * NCDIM + cellco(y)) * NCDIM + cellco(x);
    g_cellid[i] = c;
    atomicAdd(&g_ccount[c], 1);
}

__global__ void k_cscan() {
    __shared__ int sh[NCELL];
    int t = threadIdx.x;
    int v0 = g_ccount[t];
    sh[t] = v0;
    __syncthreads();
    // Hillis-Steele inclusive scan over 512
    for (int d = 1; d < NCELL; d <<= 1) {
        int v = (t >= d) ? sh[t - d] : 0;
        __syncthreads();
        sh[t] += v;
        __syncthreads();
    }
    int incl = sh[t];
    int excl = incl - v0;
    g_cstart[t] = excl;
    g_ccursor[t] = excl;
    if (t == NCELL - 1) g_cstart[NCELL] = incl;
}

__global__ void k_scatter() {
    int i = blockIdx.x * blockDim.x + threadIdx.x;
    if (i >= NA) return;
    int c = g_cellid[i];
    int p = atomicAdd(&g_ccursor[c], 1);
    g_orig[p] = i;
    g_pos4s[p] = g_pos4[i];
}

__global__ void __launch_bounds__(32) k_rows() {
    __shared__ unsigned mask[NWORDS];
    int i = blockIdx.x;
    int lane = threadIdx.x;
    for (int w = lane; w < NWORDS; w += 32) mask[w] = 0u;
    float4 pi = g_pos4[i];
    int cx = cellco(pi.x), cy = cellco(pi.y), cz = cellco(pi.z);
    __syncwarp();

    // dist < 5  <=>  RN(sqrt(d2)) < 5  <=>  d2 < nextbelow(25.0f)
    const float T = __int_as_float(0x41C7FFFF);

    int zlo = max(cz - 1, 0), zhi = min(cz + 1, 7);
    int ylo = max(cy - 1, 0), yhi = min(cy + 1, 7);
    int xlo = max(cx - 1, 0), xhi = min(cx + 1, 7);
    for (int zz = zlo; zz <= zhi; zz++)
        for (int yy = ylo; yy <= yhi; yy++)
            for (int xx = xlo; xx <= xhi; xx++) {
                int c = (zz * NCDIM + yy) * NCDIM + xx;
                int s = g_cstart[c], e = g_cstart[c + 1];
                for (int k = s + lane; k < e; k += 32) {
                    float4 pj = g_pos4s[k];
                    // dot via Eigen-style FMA chain, k ascending:
                    // dot = fma(z,z', fma(y,y', rn(x*x')))
                    float dt = __fmaf_rn(pi.z, pj.z,
                                __fmaf_rn(pi.y, pj.y,
                                 __fmul_rn(pi.x, pj.x)));
                    // d2 = (sq_i + sq_j) - 2*dot, exact op order of the reference
                    float d2 = __fsub_rn(__fadd_rn(pi.w, pj.w), __fmul_rn(2.0f, dt));
                    int j = g_orig[k];
                    if (d2 < T && j != i)
                        atomicOr(&mask[j >> 5], 1u << (j & 31));
                }
            }
    __syncwarp();

    // ordered (ascending-j) emission from the bitmask
    int cnt = 0;
    int base = i * ROWCAP;
    for (int w = 0; w < NWORDS; w++) {
        unsigned m = mask[w];  // uniform broadcast LDS
        if (m) {
            if ((m >> lane) & 1u) {
                int rank = cnt + __popc(m & ((1u << lane) - 1u));
                if (rank < ROWCAP) g_scratch[base + rank] = w * 32 + lane;
            }
            cnt += __popc(m);
        }
    }
    if (lane == 0) g_rcount[i] = min(cnt, ROWCAP);
}

__global__ void k_rscan() {
    __shared__ int wsum[32];
    const int PER = 8;  // 1024 * 8 = 8192 >= NA
    int t = threadIdx.x;
    int v[PER];
    int s = 0;
    for (int u = 0; u < PER; u++) {
        int idx = t * PER + u;
        v[u] = (idx < NA) ? g_rcount[idx] : 0;
        s += v[u];
    }
    int lane = t & 31, wid = t >> 5;
    int x = s;
    for (int d = 1; d < 32; d <<= 1) {
        int y = __shfl_up_sync(0xFFFFFFFFu, x, d);
        if (lane >= d) x += y;
    }
    if (lane == 31) wsum[wid] = x;
    __syncthreads();
    if (wid == 0) {
        int z = wsum[lane];
        int xx = z;
        for (int d = 1; d < 32; d <<= 1) {
            int y = __shfl_up_sync(0xFFFFFFFFu, xx, d);
            if (lane >= d) xx += y;
        }
        wsum[lane] = xx - z;  // exclusive warp-base
    }
    __syncthreads();
    int excl = wsum[wid] + (x - s);
    for (int u = 0; u < PER; u++) {
        int idx = t * PER + u;
        if (idx < NA) g_roff[idx] = excl;
        excl += v[u];
    }
}

__global__ void __launch_bounds__(32) k_emit(float* __restrict__ out) {
    int i = blockIdx.x;
    int lane = threadIdx.x;
    int c = g_rcount[i];
    int o = g_roff[i];
    float4 pi = g_pos4[i];
    float fi = (float)i;
    for (int k = lane; k < c; k += 32) {
        int idx = o + k;
        if (idx >= MP) break;
        int j = g_scratch[i * ROWCAP + k];
        float4 pj = g_pos4[j];
        float dx = pj.x - pi.x;
        float dy = pj.y - pi.y;
        float dz = pj.z - pi.z;
        float ds = sqrtf(dx * dx + dy * dy + dz * dz);
        out[2 * idx + 0] = fi;
        out[2 * idx + 1] = (float)j;
        out[2 * MP + idx] = (i < j) ? 1.0f : 0.0f;
        out[3 * MP + idx] = ds;
    }
}

// ---------------- launch ----------------
extern "C" void kernel_launch(void* const* d_in, const int* in_sizes, int n_in,
                              void* d_out, int out_size) {
    const float* pos = (const float*)d_in[0];
    float* out = (float*)d_out;

    k_zero<<<1024, 256>>>(out, out_size);
    k_prep<<<(NA + 255) / 256, 256>>>(pos);
    k_cscan<<<1, NCELL>>>();
    k_scatter<<<(NA + 255) / 256, 256>>>();
    k_rows<<<NA, 32>>>();
    k_rscan<<<1, 1024>>>();
    k_emit<<<NA, 32>>>(out);
}

// round 3
// speedup vs baseline: 1.5299x; 1.5299x over previous
#include <cuda_runtime.h>

#define NA      8000
#define MP      1200000
#define NCDIM   8
#define NCELL   512
#define ROWCAP  192
#define RPB     8      /* rows (warps) per block in k_rows / k_emit */

// ---------------- device scratch (no allocations allowed) ----------------
__device__ float4 g_pos4[NA];        // original order: x,y,z,|p|^2
__device__ float4 g_pos4s[NA];       // cell-sorted copy
__device__ int    g_orig[NA];        // sorted slot -> original atom index
__device__ int    g_cellid[NA];
__device__ int    g_ccount[NCELL];
__device__ int    g_cstart[NCELL + 1];
__device__ int    g_rcount[NA];
__device__ int    g_roff[NA];
__device__ int    g_scratch[NA * ROWCAP];

__device__ __forceinline__ int cellco(float x) {
    int c = (int)(x * 0.2f);
    return min(7, max(0, c));
}

// ---------------- kernels ----------------
__global__ void k_zero(float* __restrict__ out, int n) {
    int i = blockIdx.x * blockDim.x + threadIdx.x;
    int stride = gridDim.x * blockDim.x;
    int n4 = n >> 2;
    float4* o4 = (float4*)out;
    float4 z4 = make_float4(0.f, 0.f, 0.f, 0.f);
    for (int k = i; k < n4; k += stride) o4[k] = z4;
    for (int k = n4 * 4 + i; k < n; k += stride) out[k] = 0.0f;
    if (i < NCELL) g_ccount[i] = 0;
}

__global__ void k_prep(const float* __restrict__ pos) {
    int i = blockIdx.x * blockDim.x + threadIdx.x;
    if (i >= NA) return;
    float x = pos[3 * i + 0];
    float y = pos[3 * i + 1];
    float z = pos[3 * i + 2];
    // sq = (x*x + y*y) + z*z, strict fp32, NO FMA (XLA mul+reduce fusion)
    float sq = __fadd_rn(__fadd_rn(__fmul_rn(x, x), __fmul_rn(y, y)), __fmul_rn(z, z));
    g_pos4[i] = make_float4(x, y, z, sq);
    int c = (cellco(z) * NCDIM + cellco(y)) * NCDIM + cellco(x);
    g_cellid[i] = c;
    atomicAdd(&g_ccount[c], 1);
}

// fused cell-offset scan + scatter (one block, smem cursors)
__global__ void __launch_bounds__(NCELL) k_build() {
    __shared__ int sh[NCELL];
    __shared__ int cur[NCELL];
    int t = threadIdx.x;
    int v0 = g_ccount[t];
    sh[t] = v0;
    __syncthreads();
    for (int d = 1; d < NCELL; d <<= 1) {
        int v = (t >= d) ? sh[t - d] : 0;
        __syncthreads();
        sh[t] += v;
        __syncthreads();
    }
    int incl = sh[t];
    int excl = incl - v0;
    g_cstart[t] = excl;
    cur[t] = excl;
    if (t == NCELL - 1) g_cstart[NCELL] = incl;
    __syncthreads();
    for (int i = t; i < NA; i += NCELL) {
        int c = g_cellid[i];
        int p = atomicAdd(&cur[c], 1);
        g_orig[p] = i;
        g_pos4s[p] = g_pos4[i];
    }
}

__global__ void __launch_bounds__(RPB * 32) k_rows() {
    __shared__ unsigned mask[RPB][256];
    int warp = threadIdx.x >> 5;
    int lane = threadIdx.x & 31;
    int i = blockIdx.x * RPB + warp;
    unsigned* m = mask[warp];
    #pragma unroll
    for (int w = lane; w < 256; w += 32) m[w] = 0u;
    __syncwarp();

    if (i < NA) {
        float4 pi = g_pos4[i];
        int cx = cellco(pi.x), cy = cellco(pi.y), cz = cellco(pi.z);
        // dist < 5  <=>  RN(sqrt(d2)) < 5  <=>  d2 < nextbelow(25.0f)
        const float T = __int_as_float(0x41C7FFFF);
        int zlo = max(cz - 1, 0), zhi = min(cz + 1, 7);
        int ylo = max(cy - 1, 0), yhi = min(cy + 1, 7);
        int xlo = max(cx - 1, 0), xhi = min(cx + 1, 7);
        for (int zz = zlo; zz <= zhi; zz++)
            for (int yy = ylo; yy <= yhi; yy++) {
                int crow = (zz * NCDIM + yy) * NCDIM;
                int s = g_cstart[crow + xlo];
                int e = g_cstart[crow + xhi + 1];   // x-adjacent cells are contiguous
                for (int k = s + lane; k < e; k += 32) {
                    float4 pj = g_pos4s[k];
                    // Eigen-style FMA chain: dot = fma(z, fma(y, rn(x*x')))
                    float dt = __fmaf_rn(pi.z, pj.z,
                                __fmaf_rn(pi.y, pj.y,
                                 __fmul_rn(pi.x, pj.x)));
                    float d2 = __fsub_rn(__fadd_rn(pi.w, pj.w), __fmul_rn(2.0f, dt));
                    int j = g_orig[k];
                    if (d2 < T && j != i)
                        atomicOr(&m[j >> 5], 1u << (j & 31));
                }
            }
    }
    __syncwarp();

    if (i < NA) {
        // lane-parallel ordered (ascending-j) emission: lane owns words [8l, 8l+8)
        unsigned words[8];
        int cnt = 0;
        #pragma unroll
        for (int u = 0; u < 8; u++) {
            words[u] = m[lane * 8 + u];
            cnt += __popc(words[u]);
        }
        int x = cnt;
        #pragma unroll
        for (int d = 1; d < 32; d <<= 1) {
            int y = __shfl_up_sync(0xFFFFFFFFu, x, d);
            if (lane >= d) x += y;
        }
        int r = x - cnt;                                   // exclusive prefix
        int total = __shfl_sync(0xFFFFFFFFu, x, 31);
        int base = i * ROWCAP;
        #pragma unroll
        for (int u = 0; u < 8; u++) {
            unsigned mm = words[u];
            int jbase = (lane * 8 + u) * 32;
            while (mm) {
                int b = __ffs(mm) - 1;
                mm &= mm - 1;
                if (r < ROWCAP) g_scratch[base + r] = jbase + b;
                r++;
            }
        }
        if (lane == 0) g_rcount[i] = min(total, ROWCAP);
    }
}

__global__ void k_rscan() {
    __shared__ int wsum[32];
    const int PER = 8;  // 1024 * 8 = 8192 >= NA
    int t = threadIdx.x;
    int v[PER];
    int s = 0;
    for (int u = 0; u < PER; u++) {
        int idx = t * PER + u;
        v[u] = (idx < NA) ? g_rcount[idx] : 0;
        s += v[u];
    }
    int lane = t & 31, wid = t >> 5;
    int x = s;
    for (int d = 1; d < 32; d <<= 1) {
        int y = __shfl_up_sync(0xFFFFFFFFu, x, d);
        if (lane >= d) x += y;
    }
    if (lane == 31) wsum[wid] = x;
    __syncthreads();
    if (wid == 0) {
        int z = wsum[lane];
        int xx = z;
        for (int d = 1; d < 32; d <<= 1) {
            int y = __shfl_up_sync(0xFFFFFFFFu, xx, d);
            if (lane >= d) xx += y;
        }
        wsum[lane] = xx - z;  // exclusive warp-base
    }
    __syncthreads();
    int excl = wsum[wid] + (x - s);
    for (int u = 0; u < PER; u++) {
        int idx = t * PER + u;
        if (idx < NA) g_roff[idx] = excl;
        excl += v[u];
    }
}

__global__ void __launch_bounds__(RPB * 32) k_emit(float* __restrict__ out) {
    int warp = threadIdx.x >> 5;
    int lane = threadIdx.x & 31;
    int i = blockIdx.x * RPB + warp;
    if (i >= NA) return;
    int c = g_rcount[i];
    int o = g_roff[i];
    float4 pi = g_pos4[i];
    float fi = (float)i;
    for (int k = lane; k < c; k += 32) {
        int idx = o + k;
        if (idx >= MP) break;
        int j = g_scratch[i * ROWCAP + k];
        float4 pj = g_pos4[j];
        float dx = pj.x - pi.x;
        float dy = pj.y - pi.y;
        float dz = pj.z - pi.z;
        float ds = sqrtf(dx * dx + dy * dy + dz * dz);
        out[2 * idx + 0] = fi;
        out[2 * idx + 1] = (float)j;
        out[2 * MP + idx] = (i < j) ? 1.0f : 0.0f;
        out[3 * MP + idx] = ds;
    }
}

// ---------------- launch ----------------
extern "C" void kernel_launch(void* const* d_in, const int* in_sizes, int n_in,
                              void* d_out, int out_size) {
    const float* pos = (const float*)d_in[0];
    float* out = (float*)d_out;

    k_zero<<<1024, 256>>>(out, out_size);
    k_prep<<<(NA + 255) / 256, 256>>>(pos);
    k_build<<<1, NCELL>>>();
    k_rows<<<(NA + RPB - 1) / RPB, RPB * 32>>>();
    k_rscan<<<1, 1024>>>();
    k_emit<<<(NA + RPB - 1) / RPB, RPB * 32>>>(out);
}